// round 16
// baseline (speedup 1.0000x reference)
#include <cuda_runtime.h>
#include <cuda_bf16.h>
#include <math.h>
#include <stdint.h>

// L = 1 collapses the Mamba scan: h = dBu, y = dt*xin*(Bm.Cm) + D*xin, A_log dead.
#define BB      512
#define DMODEL  512
#define DSTATE  128
#define DINNER  1024
#define DTRANK  32
#define HIDDEN  256
#define XDBL_W  (DTRANK + 2*DSTATE)   // 288

// -------- scratch (no allocations; __device__ globals) --------
__device__ __nv_bfloat16 b_x   [BB*DMODEL];
__device__ __nv_bfloat16 b_win [2*DINNER*DMODEL];
__device__ __nv_bfloat16 b_wxp [XDBL_W*DINNER];
__device__ __nv_bfloat16 b_wdt [DINNER*DTRANK];
__device__ __nv_bfloat16 b_wop [DMODEL*DINNER];
__device__ __nv_bfloat16 b_wfc1[HIDDEN*DMODEL];
__device__ __nv_bfloat16 g_xinb [BB*DINNER];
__device__ __nv_bfloat16 g_zsilb[BB*DINNER];
__device__ __nv_bfloat16 g_dtb  [BB*DTRANK];   // dt-rank activations (bf16)
__device__ __nv_bfloat16 g_yb   [BB*DINNER];
__device__ __nv_bfloat16 g_o1b  [BB*DMODEL];
__device__ float g_xdbls[BB*XDBL_W];           // xdbl (fp32, full-K)
__device__ float g_bc   [BB];                  // dot(Bm, Cm) per row
__device__ float g_h1   [BB*HIDDEN];

__device__ __forceinline__ float siluf(float x) { return x / (1.f + __expf(-x)); }

__device__ __forceinline__ unsigned short bfb(float f) {
    __nv_bfloat16 h = __float2bfloat16(f);
    return *reinterpret_cast<unsigned short*>(&h);
}
__device__ __forceinline__ float bff(__nv_bfloat16 h) { return __bfloat162float(h); }

__device__ __forceinline__ void mma_bf16(float c[4],
                                         unsigned a0, unsigned a1, unsigned a2, unsigned a3,
                                         unsigned b0, unsigned b1)
{
    asm volatile(
        "mma.sync.aligned.m16n8k16.row.col.f32.bf16.bf16.f32 "
        "{%0,%1,%2,%3}, {%4,%5,%6,%7}, {%8,%9}, {%0,%1,%2,%3};"
        : "+f"(c[0]), "+f"(c[1]), "+f"(c[2]), "+f"(c[3])
        : "r"(a0), "r"(a1), "r"(a2), "r"(a3), "r"(b0), "r"(b1));
}

__device__ __forceinline__ void cp16(void* smem, const void* gmem)
{
    unsigned sa = (unsigned)__cvta_generic_to_shared(smem);
    asm volatile("cp.async.cg.shared.global [%0], [%1], 16;" :: "r"(sa), "l"(gmem));
}

__device__ __forceinline__ void ldsm_x4(unsigned& r0, unsigned& r1,
                                        unsigned& r2, unsigned& r3, const void* p)
{
    unsigned a = (unsigned)__cvta_generic_to_shared(p);
    asm volatile("ldmatrix.sync.aligned.m8n8.x4.shared.b16 {%0,%1,%2,%3}, [%4];"
                 : "=r"(r0), "=r"(r1), "=r"(r2), "=r"(r3) : "r"(a));
}

// ---------------------------------------------------------------------
// bf16 GEMM: C = A[M,K] @ W[N,K]^T, m16n8k16 mma, fp32 accum.
// BM=64, BN=64, BK=32. 256 thr = 8 warps (2m x 4n), warp tile 32x16.
// 3-stage cp.async (wait_group 1) + ldmatrix x4 fragments. No split-K.
// MODE 1: +bias(aux0) leaky -> fp32 Cf (N=HIDDEN)
// MODE 2: in_proj split -> bf16 g_xinb / g_zsilb
// MODE 3: sbc staged from g_bc (bc_kernel) + softplus + y -> bf16 g_yb
// MODE 4: x_proj -> fp32 g_xdbls (guard n<XDBL_W) + bf16 g_dtb (n<DTRANK)
// MODE 5: out_proj -> bf16 g_o1b
// ---------------------------------------------------------------------
template<int MODE>
__global__ void __launch_bounds__(256)
gemm_bf(const __nv_bfloat16* __restrict__ A, int lda,
        const __nv_bfloat16* __restrict__ W, int ldw, int wclamp,
        float* __restrict__ Cf, int N, int K,
        const float* __restrict__ aux0,
        const float* __restrict__ aux1)
{
    constexpr int LDSB = 40;           // bf16 units: 80B rows, 16B-aligned, LDSM conflict-free
    __shared__ __align__(16) __nv_bfloat16 As[3][64][LDSB];
    __shared__ __align__(16) __nv_bfloat16 Ws[3][64][LDSB];
    __shared__ float sbc[64];

    const int tid  = threadIdx.x;
    const int lane = tid & 31;
    const int wid  = tid >> 5;
    const int wm   = wid & 1;
    const int wn   = wid >> 1;
    const int g    = lane >> 2;
    const int t    = lane & 3;
    const int m0   = blockIdx.y * 64;
    const int n0   = blockIdx.x * 64;

    const int lrow = tid >> 2;         // 0..63
    const int lc8  = (tid & 3) * 8;    // bf16 col: 0,8,16,24

    const int a_r = lane & 15;
    const int a_c = (lane >> 4) * 8;
    const int b_r = wn * 16 + ((lane >> 4) << 3) + (lane & 7);
    const int b_c = ((lane >> 3) & 1) * 8;

    if (MODE == 3) {                   // stage per-row bc (from bc_kernel; 64 floats)
        if (tid < 64) sbc[tid] = g_bc[m0 + tid];
        // visibility covered by the main loop's __syncthreads
    }

    const int NK = K / 32;

    auto load_tiles = [&](int kt, int buf) {
        const int k0 = kt * 32;
        cp16(&As[buf][lrow][lc8], &A[(long)(m0 + lrow) * lda + k0 + lc8]);
        int wr = n0 + lrow;
        if (wr > wclamp) wr = wclamp;  // dup reads; padded outputs never stored
        cp16(&Ws[buf][lrow][lc8], &W[(long)wr * ldw + k0 + lc8]);
    };

    float acc[2][2][4] = {};

    load_tiles(0, 0);
    asm volatile("cp.async.commit_group;");
    if (NK > 1) {
        load_tiles(1, 1);
        asm volatile("cp.async.commit_group;");
    }

    for (int it = 0; it < NK; ++it) {
        if (it + 1 < NK) asm volatile("cp.async.wait_group 1;");
        else             asm volatile("cp.async.wait_group 0;");
        __syncthreads();

        if (it + 2 < NK) {
            load_tiles(it + 2, (it + 2) % 3);
            asm volatile("cp.async.commit_group;");
        }

        const int buf = it % 3;
        #pragma unroll
        for (int ks = 0; ks < 2; ++ks) {
            unsigned b00, b10, b01, b11;
            ldsm_x4(b00, b10, b01, b11, &Ws[buf][b_r][ks*16 + b_c]);
            #pragma unroll
            for (int mt = 0; mt < 2; ++mt) {
                unsigned a0, a1, a2, a3;
                ldsm_x4(a0, a1, a2, a3, &As[buf][wm*32 + mt*16 + a_r][ks*16 + a_c]);
                mma_bf16(acc[mt][0], a0, a1, a2, a3, b00, b10);
                mma_bf16(acc[mt][1], a0, a1, a2, a3, b01, b11);
            }
        }
    }

    // ---- epilogue ----
    #pragma unroll
    for (int mt = 0; mt < 2; ++mt) {
        #pragma unroll
        for (int nt = 0; nt < 2; ++nt) {
            const int nb = n0 + wn*16 + nt*8 + 2*t;
            #pragma unroll
            for (int half = 0; half < 2; ++half) {
                const int m = m0 + wm*32 + mt*16 + g + 8*half;
                float v0 = acc[mt][nt][2*half + 0];
                float v1 = acc[mt][nt][2*half + 1];
                if (MODE == 1) {
                    v0 += aux0[nb]; v1 += aux0[nb + 1];
                    v0 = (v0 >= 0.f) ? v0 : 0.1f * v0;
                    v1 = (v1 >= 0.f) ? v1 : 0.1f * v1;
                    *reinterpret_cast<float2*>(&Cf[(long)m*N + nb]) = make_float2(v0, v1);
                } else if (MODE == 2) {
                    unsigned pr;
                    if (n0 < DINNER) {      // uniform per CTA (1024 % 64 == 0)
                        float c0 = aux0[nb]     + aux1[2*nb + 1]     * v0;
                        float c1 = aux0[nb + 1] + aux1[2*(nb+1) + 1] * v1;
                        pr = bfb(siluf(c0)) | ((unsigned)bfb(siluf(c1)) << 16);
                        *reinterpret_cast<unsigned*>(&g_xinb[(long)m*DINNER + nb]) = pr;
                    } else {
                        pr = bfb(siluf(v0)) | ((unsigned)bfb(siluf(v1)) << 16);
                        *reinterpret_cast<unsigned*>(&g_zsilb[(long)m*DINNER + nb - DINNER]) = pr;
                    }
                } else if (MODE == 3) {
                    v0 += aux0[nb]; v1 += aux0[nb + 1];
                    float dt0 = (v0 > 20.f) ? v0 : log1pf(__expf(v0));
                    float dt1 = (v1 > 20.f) ? v1 : log1pf(__expf(v1));
                    __nv_bfloat162 xv = *reinterpret_cast<const __nv_bfloat162*>(&g_xinb [(long)m*DINNER + nb]);
                    __nv_bfloat162 zv = *reinterpret_cast<const __nv_bfloat162*>(&g_zsilb[(long)m*DINNER + nb]);
                    float bc = sbc[m - m0];
                    float y0 = (dt0 * bff(xv.x) * bc + aux1[nb]     * bff(xv.x)) * bff(zv.x);
                    float y1 = (dt1 * bff(xv.y) * bc + aux1[nb + 1] * bff(xv.y)) * bff(zv.y);
                    unsigned pr = bfb(y0) | ((unsigned)bfb(y1) << 16);
                    *reinterpret_cast<unsigned*>(&g_yb[(long)m*DINNER + nb]) = pr;
                } else if (MODE == 4) {
                    if (nb < XDBL_W)
                        *reinterpret_cast<float2*>(&g_xdbls[(long)m*XDBL_W + nb]) =
                            make_float2(v0, v1);
                    if (nb < DTRANK) {
                        unsigned pr = bfb(v0) | ((unsigned)bfb(v1) << 16);
                        *reinterpret_cast<unsigned*>(&g_dtb[m*DTRANK + nb]) = pr;
                    }
                } else { // MODE 5
                    unsigned pr = bfb(v0) | ((unsigned)bfb(v1) << 16);
                    *reinterpret_cast<unsigned*>(&g_o1b[(long)m*DMODEL + nb]) = pr;
                }
            }
        }
    }
}

// ---------------- pre-pass: fp32 -> bf16 for weights + x ----------------
__global__ void convert_kernel(const float* __restrict__ x,
                               const float* __restrict__ win,
                               const float* __restrict__ wxp,
                               const float* __restrict__ wdt,
                               const float* __restrict__ wop,
                               const float* __restrict__ wfc1)
{
    constexpr int S0 = BB*DMODEL/4;
    constexpr int S1 = 2*DINNER*DMODEL/4;
    constexpr int S2 = XDBL_W*DINNER/4;
    constexpr int S3 = DINNER*DTRANK/4;
    constexpr int S4 = DMODEL*DINNER/4;
    constexpr int S5 = HIDDEN*DMODEL/4;
    constexpr int TOT = S0+S1+S2+S3+S4+S5;

    for (int i = blockIdx.x * blockDim.x + threadIdx.x; i < TOT;
         i += gridDim.x * blockDim.x) {
        const float* src; __nv_bfloat16* dst; int j = i;
        if      (j < S0)            { src = x;    dst = b_x; }
        else if ((j -= S0) < S1)    { src = win;  dst = b_win; }
        else if ((j -= S1) < S2)    { src = wxp;  dst = b_wxp; }
        else if ((j -= S2) < S3)    { src = wdt;  dst = b_wdt; }
        else if ((j -= S3) < S4)    { src = wop;  dst = b_wop; }
        else                        { j -= S4;    src = wfc1; dst = b_wfc1; }
        float4 v = reinterpret_cast<const float4*>(src)[j];
        uint2 u;
        u.x = bfb(v.x) | ((unsigned)bfb(v.y) << 16);
        u.y = bfb(v.z) | ((unsigned)bfb(v.w) << 16);
        reinterpret_cast<uint2*>(dst)[j] = u;
    }
}

// ---- bc[b] = dot(Bm, Cm) of xdbl row; one warp per row, float4 lanes ----
__global__ void __launch_bounds__(256) bc_kernel()
{
    const int w    = threadIdx.x >> 5;
    const int lane = threadIdx.x & 31;
    const int b    = blockIdx.x * 8 + w;           // grid 64
    const float4* row4 = reinterpret_cast<const float4*>(&g_xdbls[(long)b * XDBL_W]);
    // Bm: float idx 32..159 = float4 8..39 ; Cm: 160..287 = float4 40..71
    float4 a = row4[8 + lane], c = row4[40 + lane];
    float v = a.x*c.x + a.y*c.y + a.z*c.z + a.w*c.w;
    #pragma unroll
    for (int o = 16; o > 0; o >>= 1) v += __shfl_xor_sync(0xFFFFFFFFu, v, o);
    if (lane == 0) g_bc[b] = v;
}

// out[b] = sigmoid( dot(h1[b], fc5_w) + fc5_b ); one warp per row
__global__ void __launch_bounds__(256) fc5_kernel(const float* __restrict__ w,
                                                  const float* __restrict__ bias,
                                                  float* __restrict__ out)
{
    const int wd   = threadIdx.x >> 5;
    const int lane = threadIdx.x & 31;
    const int b    = blockIdx.x * 8 + wd;          // grid 64

    const float4* h  = reinterpret_cast<const float4*>(&g_h1[b * HIDDEN]);
    const float4* wf = reinterpret_cast<const float4*>(w);
    float v = 0.f;
    #pragma unroll
    for (int i = 0; i < HIDDEN / 128; ++i) {       // 2 float4 per lane
        float4 a = h[lane + 32*i], c = wf[lane + 32*i];
        v += a.x*c.x + a.y*c.y + a.z*c.z + a.w*c.w;
    }
    #pragma unroll
    for (int o = 16; o > 0; o >>= 1) v += __shfl_xor_sync(0xFFFFFFFFu, v, o);
    if (lane == 0)
        out[b] = 1.f / (1.f + __expf(-(v + bias[0])));
}

extern "C" void kernel_launch(void* const* d_in, const int* in_sizes, int n_in,
                              void* d_out, int out_size)
{
    const float* x         = (const float*)d_in[0];
    const float* in_proj_w = (const float*)d_in[1];
    const float* conv_w    = (const float*)d_in[2];
    const float* conv_b    = (const float*)d_in[3];
    const float* x_proj_w  = (const float*)d_in[4];
    const float* dt_proj_w = (const float*)d_in[5];
    const float* dt_proj_b = (const float*)d_in[6];
    // d_in[7] = A_log: dead (h0 = 0, L = 1)
    const float* Dp        = (const float*)d_in[8];
    const float* out_projw = (const float*)d_in[9];
    const float* fc1_w     = (const float*)d_in[10];
    const float* fc1_b     = (const float*)d_in[11];
    const float* fc5_w     = (const float*)d_in[12];
    const float* fc5_b     = (const float*)d_in[13];
    float* out = (float*)d_out;

    void *xb, *wib, *wxb, *wdb, *wob, *wfb, *xinb, *dtb, *yb, *o1b, *h1;
    cudaGetSymbolAddress(&xb,  b_x);     cudaGetSymbolAddress(&wib, b_win);
    cudaGetSymbolAddress(&wxb, b_wxp);   cudaGetSymbolAddress(&wdb, b_wdt);
    cudaGetSymbolAddress(&wob, b_wop);   cudaGetSymbolAddress(&wfb, b_wfc1);
    cudaGetSymbolAddress(&xinb, g_xinb); cudaGetSymbolAddress(&dtb, g_dtb);
    cudaGetSymbolAddress(&yb,  g_yb);    cudaGetSymbolAddress(&o1b, g_o1b);
    cudaGetSymbolAddress(&h1,  g_h1);

    const dim3 blk(256);

    // 0. fp32 -> bf16 pre-pass (weights + x)
    convert_kernel<<<1024, 256>>>(x, in_proj_w, x_proj_w, dt_proj_w, out_projw, fc1_w);
    // 1. in_proj (N=2048,K=512) + conv + silu split -> bf16 xin,zsil   [256 CTAs]
    gemm_bf<2><<<dim3(32, 8), blk>>>((const __nv_bfloat16*)xb, DMODEL,
        (const __nv_bfloat16*)wib, DMODEL, 2*DINNER - 1,
        nullptr, 2*DINNER, DMODEL, conv_b, conv_w);
    // 2. x_proj (N=288->320,K=1024) -> fp32 g_xdbls + bf16 dtb          [40 CTAs]
    gemm_bf<4><<<dim3(5, 8), blk>>>((const __nv_bfloat16*)xinb, DINNER,
        (const __nv_bfloat16*)wxb, DINNER, XDBL_W - 1,
        nullptr, XDBL_W, DINNER, nullptr, nullptr);
    // 3. bc[b] from g_xdbls                                            [64 CTAs]
    bc_kernel<<<BB/8, 256>>>();
    // 4. dt_proj (K=32) + sbc stage + softplus + y -> bf16 g_yb        [128 CTAs]
    gemm_bf<3><<<dim3(16, 8), blk>>>((const __nv_bfloat16*)dtb, DTRANK,
        (const __nv_bfloat16*)wdb, DTRANK, DINNER - 1,
        nullptr, DINNER, DTRANK, dt_proj_b, Dp);
    // 5. out_proj (N=512,K=1024) -> bf16 g_o1b                          [64 CTAs]
    gemm_bf<5><<<dim3(8, 8), blk>>>((const __nv_bfloat16*)yb, DINNER,
        (const __nv_bfloat16*)wob, DINNER, DMODEL - 1,
        nullptr, DMODEL, DINNER, nullptr, nullptr);
    // 6. fc1 (N=256,K=512) + bias + leaky -> fp32 h1                    [32 CTAs]
    gemm_bf<1><<<dim3(4, 8), blk>>>((const __nv_bfloat16*)o1b, DMODEL,
        (const __nv_bfloat16*)wfb, DMODEL, HIDDEN - 1,
        (float*)h1, HIDDEN, DMODEL, fc1_b, nullptr);
    // 7. fc5 + sigmoid -> out (B,1)
    fc5_kernel<<<BB/8, 256>>>(fc5_w, fc5_b, out);
}

// round 17
// speedup vs baseline: 1.1957x; 1.1957x over previous
#include <cuda_runtime.h>
#include <cuda_bf16.h>
#include <math.h>
#include <stdint.h>

// L = 1 collapses the Mamba scan: h = dBu, y = dt*xin*(Bm.Cm) + D*xin, A_log dead.
#define BB      512
#define DMODEL  512
#define DSTATE  128
#define DINNER  1024
#define DTRANK  32
#define HIDDEN  256
#define XDBL_W  (DTRANK + 2*DSTATE)   // 288
#define SPLK    4

// -------- scratch (no allocations; __device__ globals) --------
__device__ __nv_bfloat16 b_x   [BB*DMODEL];
__device__ __nv_bfloat16 b_win [2*DINNER*DMODEL];
__device__ __nv_bfloat16 b_wxp [XDBL_W*DINNER];
__device__ __nv_bfloat16 b_wdt [DINNER*DTRANK];
__device__ __nv_bfloat16 b_wop [DMODEL*DINNER];
__device__ __nv_bfloat16 b_wfc1[HIDDEN*DMODEL];
__device__ __nv_bfloat16 g_xinb [BB*DINNER];
__device__ __nv_bfloat16 g_zsilb[BB*DINNER];
__device__ __nv_bfloat16 g_dtb  [BB*DTRANK];   // summed dt activations (bf16)
__device__ __nv_bfloat16 g_yb   [BB*DINNER];
__device__ __nv_bfloat16 g_o1b  [BB*DMODEL];
__device__ float g_xdblp[SPLK*BB*XDBL_W];      // x_proj split-K fp32 partials
__device__ float g_xdbls[BB*XDBL_W];           // summed xdbl (fp32)
__device__ float g_opart[SPLK*BB*DMODEL];      // out_proj split-K fp32 partials
__device__ float g_h1   [BB*HIDDEN];

__device__ __forceinline__ float siluf(float x) { return x / (1.f + __expf(-x)); }

__device__ __forceinline__ unsigned short bfb(float f) {
    __nv_bfloat16 h = __float2bfloat16(f);
    return *reinterpret_cast<unsigned short*>(&h);
}
__device__ __forceinline__ float bff(__nv_bfloat16 h) { return __bfloat162float(h); }

__device__ __forceinline__ void mma_bf16(float c[4],
                                         unsigned a0, unsigned a1, unsigned a2, unsigned a3,
                                         unsigned b0, unsigned b1)
{
    asm volatile(
        "mma.sync.aligned.m16n8k16.row.col.f32.bf16.bf16.f32 "
        "{%0,%1,%2,%3}, {%4,%5,%6,%7}, {%8,%9}, {%0,%1,%2,%3};"
        : "+f"(c[0]), "+f"(c[1]), "+f"(c[2]), "+f"(c[3])
        : "r"(a0), "r"(a1), "r"(a2), "r"(a3), "r"(b0), "r"(b1));
}

__device__ __forceinline__ void cp16(void* smem, const void* gmem)
{
    unsigned sa = (unsigned)__cvta_generic_to_shared(smem);
    asm volatile("cp.async.cg.shared.global [%0], [%1], 16;" :: "r"(sa), "l"(gmem));
}

__device__ __forceinline__ void ldsm_x4(unsigned& r0, unsigned& r1,
                                        unsigned& r2, unsigned& r3, const void* p)
{
    unsigned a = (unsigned)__cvta_generic_to_shared(p);
    asm volatile("ldmatrix.sync.aligned.m8n8.x4.shared.b16 {%0,%1,%2,%3}, [%4];"
                 : "=r"(r0), "=r"(r1), "=r"(r2), "=r"(r3) : "r"(a));
}

// ---------------------------------------------------------------------
// bf16 GEMM: C = A[M,K] @ W[N,K]^T, m16n8k16 mma, fp32 accum.
// BM=64, BN=64, BK=32. 256 thr = 8 warps (2m x 4n), warp tile 32x16.
// 3-stage cp.async (wait_group 1) + ldmatrix x4 fragments.
// SPLITZ>1: blockIdx.z = K-slice; C -> fp32 partial plane z.
// MODE 0: fp32 store (+n guard)  1: +bias leaky -> fp32
// MODE 2: in_proj split -> bf16 xin/zsil
// MODE 3: inline bc (batched loads, overlapped w/ prefetch) + softplus + y
// ---------------------------------------------------------------------
template<int MODE, int SPLITZ>
__global__ void __launch_bounds__(256)
gemm_bf(const __nv_bfloat16* __restrict__ A, int lda,
        const __nv_bfloat16* __restrict__ W, int ldw, int wclamp,
        float* __restrict__ Cf, int N, int K, long cplane,
        const float* __restrict__ aux0,
        const float* __restrict__ aux1,
        __nv_bfloat16* __restrict__ out2)
{
    constexpr int LDSB = 40;           // bf16 units: 80B rows, 16B-aligned, LDSM conflict-free
    __shared__ __align__(16) __nv_bfloat16 As[3][64][LDSB];
    __shared__ __align__(16) __nv_bfloat16 Ws[3][64][LDSB];
    __shared__ float sbc[64];

    const int tid  = threadIdx.x;
    const int lane = tid & 31;
    const int wid  = tid >> 5;
    const int wm   = wid & 1;
    const int wn   = wid >> 1;
    const int g    = lane >> 2;
    const int t    = lane & 3;
    const int m0   = blockIdx.y * 64;
    const int n0   = blockIdx.x * 64;

    const int z = (SPLITZ > 1) ? blockIdx.z : 0;
    const __nv_bfloat16* Az = A + (long)z * K;
    const __nv_bfloat16* Wz = W + (long)z * K;
    float* Cz = Cf + ((SPLITZ > 1) ? (long)z * cplane : 0L);

    const int lrow = tid >> 2;         // 0..63
    const int lc8  = (tid & 3) * 8;    // bf16 col: 0,8,16,24

    const int a_r = lane & 15;
    const int a_c = (lane >> 4) * 8;
    const int b_r = wn * 16 + ((lane >> 4) << 3) + (lane & 7);
    const int b_c = ((lane >> 3) & 1) * 8;

    const int NK = K / 32;

    auto load_tiles = [&](int kt, int buf) {
        const int k0 = kt * 32;
        cp16(&As[buf][lrow][lc8], &Az[(long)(m0 + lrow) * lda + k0 + lc8]);
        int wr = n0 + lrow;
        if (wr > wclamp) wr = wclamp;  // dup reads; padded outputs never stored
        cp16(&Ws[buf][lrow][lc8], &Wz[(long)wr * ldw + k0 + lc8]);
    };

    float acc[2][2][4] = {};

    load_tiles(0, 0);
    asm volatile("cp.async.commit_group;");
    if (NK > 1) {
        load_tiles(1, 1);
        asm volatile("cp.async.commit_group;");
    }

    // MODE3 prologue (after prefetch issue, overlaps it): bc for this CTA's
    // 64 rows. Warp w owns rows w*8..w*8+7. ALL 16 float4 loads are issued
    // back-to-back (MLP=16, one latency exposure), THEN the 8 independent
    // shfl-reduce chains run. Same per-row float4 dot order as the old
    // bc_kernel -> bit-identical results.
    if (MODE == 3) {
        float4 aB[8], aC[8];
        #pragma unroll
        for (int rr = 0; rr < 8; ++rr) {
            const float4* row4 =
                reinterpret_cast<const float4*>(&g_xdbls[(long)(m0 + wid*8 + rr) * XDBL_W]);
            aB[rr] = row4[8 + lane];   // Bm: floats 32..159
            aC[rr] = row4[40 + lane];  // Cm: floats 160..287
        }
        float v[8];
        #pragma unroll
        for (int rr = 0; rr < 8; ++rr)
            v[rr] = aB[rr].x*aC[rr].x + aB[rr].y*aC[rr].y
                  + aB[rr].z*aC[rr].z + aB[rr].w*aC[rr].w;
        #pragma unroll
        for (int o = 16; o > 0; o >>= 1) {
            #pragma unroll
            for (int rr = 0; rr < 8; ++rr)
                v[rr] += __shfl_xor_sync(0xFFFFFFFFu, v[rr], o);
        }
        if (lane < 8) sbc[wid*8 + lane] = v[lane];   // lane rr holds full sum of row rr
        // cross-warp visibility: covered by the main loop's __syncthreads
    }

    for (int it = 0; it < NK; ++it) {
        if (it + 1 < NK) asm volatile("cp.async.wait_group 1;");
        else             asm volatile("cp.async.wait_group 0;");
        __syncthreads();

        if (it + 2 < NK) {
            load_tiles(it + 2, (it + 2) % 3);
            asm volatile("cp.async.commit_group;");
        }

        const int buf = it % 3;
        #pragma unroll
        for (int ks = 0; ks < 2; ++ks) {
            unsigned b00, b10, b01, b11;
            ldsm_x4(b00, b10, b01, b11, &Ws[buf][b_r][ks*16 + b_c]);
            #pragma unroll
            for (int mt = 0; mt < 2; ++mt) {
                unsigned a0, a1, a2, a3;
                ldsm_x4(a0, a1, a2, a3, &As[buf][wm*32 + mt*16 + a_r][ks*16 + a_c]);
                mma_bf16(acc[mt][0], a0, a1, a2, a3, b00, b10);
                mma_bf16(acc[mt][1], a0, a1, a2, a3, b01, b11);
            }
        }
    }

    // ---- epilogue ----
    #pragma unroll
    for (int mt = 0; mt < 2; ++mt) {
        #pragma unroll
        for (int nt = 0; nt < 2; ++nt) {
            const int nb = n0 + wn*16 + nt*8 + 2*t;
            #pragma unroll
            for (int half = 0; half < 2; ++half) {
                const int m = m0 + wm*32 + mt*16 + g + 8*half;
                float v0 = acc[mt][nt][2*half + 0];
                float v1 = acc[mt][nt][2*half + 1];
                if (MODE == 0) {
                    if (nb < N - 1)
                        *reinterpret_cast<float2*>(&Cz[(long)m*N + nb]) = make_float2(v0, v1);
                } else if (MODE == 1) {
                    v0 += aux0[nb]; v1 += aux0[nb + 1];
                    v0 = (v0 >= 0.f) ? v0 : 0.1f * v0;
                    v1 = (v1 >= 0.f) ? v1 : 0.1f * v1;
                    *reinterpret_cast<float2*>(&Cz[(long)m*N + nb]) = make_float2(v0, v1);
                } else if (MODE == 2) {
                    unsigned pr;
                    if (n0 < DINNER) {      // uniform per CTA (1024 % 64 == 0)
                        float c0 = aux0[nb]     + aux1[2*nb + 1]     * v0;
                        float c1 = aux0[nb + 1] + aux1[2*(nb+1) + 1] * v1;
                        pr = bfb(siluf(c0)) | ((unsigned)bfb(siluf(c1)) << 16);
                        *reinterpret_cast<unsigned*>(&g_xinb[(long)m*DINNER + nb]) = pr;
                    } else {
                        pr = bfb(siluf(v0)) | ((unsigned)bfb(siluf(v1)) << 16);
                        *reinterpret_cast<unsigned*>(&out2[(long)m*DINNER + nb - DINNER]) = pr;
                    }
                } else { // MODE 3
                    v0 += aux0[nb]; v1 += aux0[nb + 1];
                    float dt0 = (v0 > 20.f) ? v0 : log1pf(__expf(v0));
                    float dt1 = (v1 > 20.f) ? v1 : log1pf(__expf(v1));
                    __nv_bfloat162 xv = *reinterpret_cast<const __nv_bfloat162*>(&g_xinb [(long)m*DINNER + nb]);
                    __nv_bfloat162 zv = *reinterpret_cast<const __nv_bfloat162*>(&g_zsilb[(long)m*DINNER + nb]);
                    float bc = sbc[m - m0];
                    float y0 = (dt0 * bff(xv.x) * bc + aux1[nb]     * bff(xv.x)) * bff(zv.x);
                    float y1 = (dt1 * bff(xv.y) * bc + aux1[nb + 1] * bff(xv.y)) * bff(zv.y);
                    unsigned pr = bfb(y0) | ((unsigned)bfb(y1) << 16);
                    *reinterpret_cast<unsigned*>(&g_yb[(long)m*DINNER + nb]) = pr;
                }
            }
        }
    }
}

// ---------------- pre-pass: fp32 -> bf16 for weights + x ----------------
__global__ void convert_kernel(const float* __restrict__ x,
                               const float* __restrict__ win,
                               const float* __restrict__ wxp,
                               const float* __restrict__ wdt,
                               const float* __restrict__ wop,
                               const float* __restrict__ wfc1)
{
    constexpr int S0 = BB*DMODEL/4;
    constexpr int S1 = 2*DINNER*DMODEL/4;
    constexpr int S2 = XDBL_W*DINNER/4;
    constexpr int S3 = DINNER*DTRANK/4;
    constexpr int S4 = DMODEL*DINNER/4;
    constexpr int S5 = HIDDEN*DMODEL/4;
    constexpr int TOT = S0+S1+S2+S3+S4+S5;

    for (int i = blockIdx.x * blockDim.x + threadIdx.x; i < TOT;
         i += gridDim.x * blockDim.x) {
        const float* src; __nv_bfloat16* dst; int j = i;
        if      (j < S0)            { src = x;    dst = b_x; }
        else if ((j -= S0) < S1)    { src = win;  dst = b_win; }
        else if ((j -= S1) < S2)    { src = wxp;  dst = b_wxp; }
        else if ((j -= S2) < S3)    { src = wdt;  dst = b_wdt; }
        else if ((j -= S3) < S4)    { src = wop;  dst = b_wop; }
        else                        { j -= S4;    src = wfc1; dst = b_wfc1; }
        float4 v = reinterpret_cast<const float4*>(src)[j];
        uint2 u;
        u.x = bfb(v.x) | ((unsigned)bfb(v.y) << 16);
        u.y = bfb(v.z) | ((unsigned)bfb(v.w) << 16);
        reinterpret_cast<uint2*>(dst)[j] = u;
    }
}

// ---- flat float4 sum of SPLK xdbl planes -> g_xdbls (+ bf16 dt cols) ----
__global__ void __launch_bounds__(256) sum_xdbl_kernel()
{
    const int i = blockIdx.x * 256 + threadIdx.x;
    const long plane4 = (long)BB * XDBL_W / 4;     // 36864
    const float4* p = reinterpret_cast<const float4*>(g_xdblp);
    float4 s = p[i];
    #pragma unroll
    for (int z = 1; z < SPLK; ++z) {
        float4 v = p[i + z*plane4];
        s.x += v.x; s.y += v.y; s.z += v.z; s.w += v.w;
    }
    reinterpret_cast<float4*>(g_xdbls)[i] = s;

    const int c = (i % (XDBL_W/4)) * 4;            // 72 float4 per row
    if (c < DTRANK) {
        const int r = i / (XDBL_W/4);
        uint2 u;
        u.x = bfb(s.x) | ((unsigned)bfb(s.y) << 16);
        u.y = bfb(s.z) | ((unsigned)bfb(s.w) << 16);
        *reinterpret_cast<uint2*>(&g_dtb[r*DTRANK + c]) = u;
    }
}

// out1_b (bf16) = sum of SPLK fp32 out_proj planes
__global__ void reduce_kernel()
{
    const int i = blockIdx.x * blockDim.x + threadIdx.x;   // 65536 float4s
    const float4* p = reinterpret_cast<const float4*>(g_opart);
    const long plane4 = (long)BB * DMODEL / 4;
    float4 s = p[i];
    #pragma unroll
    for (int z = 1; z < SPLK; ++z) {
        float4 v = p[i + z*plane4];
        s.x += v.x; s.y += v.y; s.z += v.z; s.w += v.w;
    }
    uint2 u;
    u.x = bfb(s.x) | ((unsigned)bfb(s.y) << 16);
    u.y = bfb(s.z) | ((unsigned)bfb(s.w) << 16);
    reinterpret_cast<uint2*>(g_o1b)[i] = u;
}

// out[b] = sigmoid( dot(h1[b], fc5_w) + fc5_b ); one warp per row
__global__ void __launch_bounds__(256) fc5_kernel(const float* __restrict__ w,
                                                  const float* __restrict__ bias,
                                                  float* __restrict__ out)
{
    const int wd   = threadIdx.x >> 5;
    const int lane = threadIdx.x & 31;
    const int b    = blockIdx.x * 8 + wd;          // grid 64

    const float4* h  = reinterpret_cast<const float4*>(&g_h1[b * HIDDEN]);
    const float4* wf = reinterpret_cast<const float4*>(w);
    float v = 0.f;
    #pragma unroll
    for (int i = 0; i < HIDDEN / 128; ++i) {       // 2 float4 per lane
        float4 a = h[lane + 32*i], c = wf[lane + 32*i];
        v += a.x*c.x + a.y*c.y + a.z*c.z + a.w*c.w;
    }
    #pragma unroll
    for (int o = 16; o > 0; o >>= 1) v += __shfl_xor_sync(0xFFFFFFFFu, v, o);
    if (lane == 0)
        out[b] = 1.f / (1.f + __expf(-(v + bias[0])));
}

extern "C" void kernel_launch(void* const* d_in, const int* in_sizes, int n_in,
                              void* d_out, int out_size)
{
    const float* x         = (const float*)d_in[0];
    const float* in_proj_w = (const float*)d_in[1];
    const float* conv_w    = (const float*)d_in[2];
    const float* conv_b    = (const float*)d_in[3];
    const float* x_proj_w  = (const float*)d_in[4];
    const float* dt_proj_w = (const float*)d_in[5];
    const float* dt_proj_b = (const float*)d_in[6];
    // d_in[7] = A_log: dead (h0 = 0, L = 1)
    const float* Dp        = (const float*)d_in[8];
    const float* out_projw = (const float*)d_in[9];
    const float* fc1_w     = (const float*)d_in[10];
    const float* fc1_b     = (const float*)d_in[11];
    const float* fc5_w     = (const float*)d_in[12];
    const float* fc5_b     = (const float*)d_in[13];
    float* out = (float*)d_out;

    void *xb, *wib, *wxb, *wdb, *wob, *wfb, *xinb, *zsb, *dtb, *yb, *o1b, *xdp, *opr, *h1;
    cudaGetSymbolAddress(&xb,  b_x);     cudaGetSymbolAddress(&wib, b_win);
    cudaGetSymbolAddress(&wxb, b_wxp);   cudaGetSymbolAddress(&wdb, b_wdt);
    cudaGetSymbolAddress(&wob, b_wop);   cudaGetSymbolAddress(&wfb, b_wfc1);
    cudaGetSymbolAddress(&xinb, g_xinb); cudaGetSymbolAddress(&zsb, g_zsilb);
    cudaGetSymbolAddress(&dtb, g_dtb);   cudaGetSymbolAddress(&yb,  g_yb);
    cudaGetSymbolAddress(&o1b, g_o1b);   cudaGetSymbolAddress(&xdp, g_xdblp);
    cudaGetSymbolAddress(&opr, g_opart); cudaGetSymbolAddress(&h1,  g_h1);

    const long XP = (long)BB * XDBL_W;
    const long OP = (long)BB * DMODEL;
    const dim3 blk(256);

    // 0. fp32 -> bf16 pre-pass (weights + x)
    convert_kernel<<<1024, 256>>>(x, in_proj_w, x_proj_w, dt_proj_w, out_projw, fc1_w);
    // 1. in_proj (N=2048,K=512) + conv + silu split -> bf16 xin,zsil   [256 CTAs]
    gemm_bf<2,1><<<dim3(32, 8), blk>>>((const __nv_bfloat16*)xb, DMODEL,
        (const __nv_bfloat16*)wib, DMODEL, 2*DINNER - 1,
        nullptr, 2*DINNER, DMODEL, 0, conv_b, conv_w, (__nv_bfloat16*)zsb);
    // 2. x_proj split-K x4 (K=256 slices) -> fp32 partials             [160 CTAs]
    gemm_bf<0,SPLK><<<dim3(5, 8, SPLK), blk>>>((const __nv_bfloat16*)xinb, DINNER,
        (const __nv_bfloat16*)wxb, DINNER, XDBL_W - 1,
        (float*)xdp, XDBL_W, DINNER/SPLK, XP, nullptr, nullptr, nullptr);
    // 3. flat plane sum -> g_xdbls + bf16 dt activations               [144 CTAs]
    sum_xdbl_kernel<<<(BB*XDBL_W/4)/256, 256>>>();
    // 4. dt_proj (K=32) + inline batched bc + softplus + y -> bf16 y   [128 CTAs]
    gemm_bf<3,1><<<dim3(16, 8), blk>>>((const __nv_bfloat16*)dtb, DTRANK,
        (const __nv_bfloat16*)wdb, DTRANK, DINNER - 1,
        nullptr, DINNER, DTRANK, 0, dt_proj_b, Dp, nullptr);
    // 5. out_proj split-K x4 -> fp32 partials                          [256 CTAs]
    gemm_bf<0,SPLK><<<dim3(8, 8, SPLK), blk>>>((const __nv_bfloat16*)yb, DINNER,
        (const __nv_bfloat16*)wob, DINNER, DMODEL - 1,
        (float*)opr, DMODEL, DINNER/SPLK, OP, nullptr, nullptr, nullptr);
    // 6. out1_b = bf16(sum of planes)
    reduce_kernel<<<256, 256>>>();
    // 7. fc1 (N=256,K=512) + bias + leaky -> fp32 h1                   [32 CTAs]
    gemm_bf<1,1><<<dim3(4, 8), blk>>>((const __nv_bfloat16*)o1b, DMODEL,
        (const __nv_bfloat16*)wfb, DMODEL, HIDDEN - 1,
        (float*)h1, HIDDEN, DMODEL, 0, fc1_b, nullptr, nullptr);
    // 8. fc5 + sigmoid -> out (B,1)
    fc5_kernel<<<BB/8, 256>>>(fc5_w, fc5_b, out);
}